// round 15
// baseline (speedup 1.0000x reference)
#include <cuda_runtime.h>
#include <cuda_bf16.h>
#include <cuda_fp8.h>
#include <cstdint>

// Problem constants
#define B_   2
#define T_   4096
#define C_   1024
#define H_   16
#define D_   64
#define NTOK 8192   // B_*T_

// ---------------------------------------------------------------------------
// Scratch (static device globals; no runtime allocation allowed)
// ---------------------------------------------------------------------------
__device__ __nv_bfloat16 g_xs  [(size_t)NTOK * 2048];   // x split [hi|lo]
__device__ uint8_t       g_x8  [(size_t)NTOK * 2048];   // x e4m3 [hi | lo*2^9]
__device__ __nv_bfloat16 g_wqkv[(size_t)3 * 1024 * 2048]; // Wq/Wk/Wv^T split
__device__ __nv_bfloat16 g_wo  [(size_t)1024 * 2048];
__device__ uint8_t       g_wo8 [(size_t)1024 * 2048];   // wo e4m3 [hi*2^4 | lo*2^13]
__device__ __nv_bfloat16 g_wcr [(size_t)3 * 1024 * 2048]; // Wc slices row-split
__device__ __nv_bfloat16 g_wf  [(size_t)3072 * 2048];   // fused W^T split [n,2k]
__device__ uint8_t       g_wf8 [(size_t)3072 * 2048];   // wf e4m3 [hi*2^4 | lo*2^13]
__device__ float g_bf[3072];                            // fused biases
__device__ float g_zero[1024];                          // zero bias (static 0)
// q/k/v as split bf16: [s][bh][t][128] rows = hi(64) | lo(64)
__device__ __nv_bfloat16 g_qkvb[(size_t)3 * 32 * T_ * 128];
__device__ float g_o0[(size_t)B_ * H_ * T_ * D_];
__device__ float g_o1[(size_t)B_ * H_ * (T_ / 2) * D_];
__device__ float g_o2[(size_t)B_ * H_ * (T_ / 4) * D_];
__device__ float g_l0[B_ * H_ * T_];
__device__ float g_l1[B_ * H_ * (T_ / 2)];
__device__ float g_l2[B_ * H_ * (T_ / 4)];
__device__ __nv_bfloat16 g_y2[(size_t)NTOK * 2048];     // combined split [hi|lo]
__device__ uint8_t       g_y8[(size_t)NTOK * 2048];     // y e4m3 [hi | lo*2^9]

// ---------------------------------------------------------------------------
// PTX helpers
// ---------------------------------------------------------------------------
__device__ __forceinline__ uint32_t smem_u32(const void* p) {
    uint32_t a;
    asm("{ .reg .u64 t; cvta.to.shared.u64 t, %1; cvt.u32.u64 %0, t; }"
        : "=r"(a) : "l"(p));
    return a;
}
__device__ __forceinline__ void cp16(uint32_t dst, const void* src) {
    asm volatile("cp.async.cg.shared.global [%0], [%1], 16;\n"
                 :: "r"(dst), "l"(src));
}
__device__ __forceinline__ void ldm4(uint32_t* r, uint32_t a) {
    asm volatile("ldmatrix.sync.aligned.m8n8.x4.shared.b16 {%0,%1,%2,%3}, [%4];"
                 : "=r"(r[0]), "=r"(r[1]), "=r"(r[2]), "=r"(r[3]) : "r"(a));
}
__device__ __forceinline__ void mma16816(float* c, const uint32_t* a,
                                         const uint32_t* b) {
    asm volatile(
        "mma.sync.aligned.m16n8k16.row.col.f32.bf16.bf16.f32 "
        "{%0,%1,%2,%3}, {%4,%5,%6,%7}, {%8,%9}, {%0,%1,%2,%3};"
        : "+f"(c[0]), "+f"(c[1]), "+f"(c[2]), "+f"(c[3])
        : "r"(a[0]), "r"(a[1]), "r"(a[2]), "r"(a[3]), "r"(b[0]), "r"(b[1]));
}
__device__ __forceinline__ void mma_fp8(float* c, const uint32_t* a,
                                        const uint32_t* b) {
    asm volatile(
        "mma.sync.aligned.m16n8k32.row.col.f32.e4m3.e4m3.f32 "
        "{%0,%1,%2,%3}, {%4,%5,%6,%7}, {%8,%9}, {%0,%1,%2,%3};"
        : "+f"(c[0]), "+f"(c[1]), "+f"(c[2]), "+f"(c[3])
        : "r"(a[0]), "r"(a[1]), "r"(a[2]), "r"(a[3]), "r"(b[0]), "r"(b[1]));
}
__device__ __forceinline__ uint8_t to_e4m3(float v) {
    return (uint8_t)__nv_cvt_float_to_fp8(v, __NV_SATFINITE, __NV_E4M3);
}
// exp2 on the FMA pipe
__device__ __forceinline__ float fexp2(float t) {
    t = fmaxf(t, -80.f);
    float fl = floorf(t);
    float f = t - fl;
    float p = 0.0013276471f;
    p = fmaf(p, f, 0.0096788383f);
    p = fmaf(p, f, 0.0555072548f);
    p = fmaf(p, f, 0.2402211502f);
    p = fmaf(p, f, 0.6931469902f);
    p = fmaf(p, f, 1.0f);
    int e = (int)fl;
    return p * __int_as_float((e + 127) << 23);
}

// ---------------------------------------------------------------------------
// 3-term split-bf16 HMMA GEMM (kept for fused-weight prep only).
// mode 3: transposed split store.
// ---------------------------------------------------------------------------
#define STAGEB 20480
#define GEMM_SMEM (4 * STAGEB)

__global__ __launch_bounds__(256) void gemm_mma(
    const __nv_bfloat16* __restrict__ A0, int lda, int aHi, int aLo,
    const __nv_bfloat16* __restrict__ Bt0, int ldb, int bHi, int bLo,
    const float* __restrict__ bias, void* __restrict__ outp0,
    int ldc, int oLo, int NKC, int mode, float scale,
    size_t zbA, size_t zbB, size_t zbO)
{
    const __nv_bfloat16* A =
        (const __nv_bfloat16*)((const char*)A0 + (size_t)blockIdx.z * zbA);
    const __nv_bfloat16* Bt =
        (const __nv_bfloat16*)((const char*)Bt0 + (size_t)blockIdx.z * zbB);
    void* outp = (char*)outp0 + (size_t)blockIdx.z * zbO;

    extern __shared__ __align__(128) char smx[];
    const uint32_t su = smem_u32(smx);
    const int tid = threadIdx.x;
    const int warp = tid >> 5, lane = tid & 31;
    const int wm = warp >> 1, wn = warp & 1;
    const int m0 = blockIdx.y * 128, n0 = blockIdx.x * 128;
    const int NC = 3 * NKC;

    float acc[2][8][4];
#pragma unroll
    for (int i = 0; i < 2; i++)
#pragma unroll
        for (int j = 0; j < 8; j++)
#pragma unroll
            for (int q = 0; q < 4; q++) acc[i][j][q] = 0.f;

    auto loads = [&](int c, int s) {
        int ka, kb;
        if (c < NKC)            { ka = aHi + c * 32;            kb = bHi + c * 32; }
        else if (c < 2 * NKC)   { int k2 = c - NKC;     ka = aHi + k2 * 32; kb = bLo + k2 * 32; }
        else                    { int k2 = c - 2 * NKC; ka = aLo + k2 * 32; kb = bHi + k2 * 32; }
        uint32_t sa = su + (uint32_t)s * STAGEB;
        uint32_t sb = sa + 10240;
#pragma unroll
        for (int j = 0; j < 2; j++) {
            int f = tid + j * 256;
            int r = f >> 2, si = (f & 3) * 16;
            cp16(sa + r * 80 + si,
                 (const char*)(A + (size_t)(m0 + r) * lda + ka) + si);
            cp16(sb + r * 80 + si,
                 (const char*)(Bt + (size_t)(n0 + r) * ldb + kb) + si);
        }
        asm volatile("cp.async.commit_group;\n" ::: "memory");
    };

    loads(0, 0); loads(1, 1); loads(2, 2);

#pragma unroll 1
    for (int c = 0; c < NC; c++) {
        asm volatile("cp.async.wait_group 2;\n" ::: "memory");
        __syncthreads();
        if (c + 3 < NC) loads(c + 3, (c + 3) & 3);

        uint32_t sa = su + (uint32_t)(c & 3) * STAGEB;
        uint32_t sb = sa + 10240;
#pragma unroll
        for (int kk = 0; kk < 2; kk++) {
            uint32_t af[2][4];
#pragma unroll
            for (int mm = 0; mm < 2; mm++) {
                uint32_t addr = sa +
                    (uint32_t)(wm * 32 + mm * 16 + (lane & 15)) * 80 +
                    ((lane >> 4) << 4) + kk * 32;
                ldm4(af[mm], addr);
            }
            uint32_t bf[4][4];
#pragma unroll
            for (int nb = 0; nb < 4; nb++) {
                int rown = wn * 64 + nb * 16 + ((lane >> 4) & 1) * 8 + (lane & 7);
                uint32_t addr = sb + (uint32_t)rown * 80 +
                    (((lane >> 3) & 1) << 4) + kk * 32;
                ldm4(bf[nb], addr);
            }
#pragma unroll
            for (int mm = 0; mm < 2; mm++)
#pragma unroll
                for (int nn = 0; nn < 8; nn++)
                    mma16816(acc[mm][nn], af[mm], &bf[nn >> 1][(nn & 1) * 2]);
        }
    }

    const int r0 = m0 + wm * 32 + (lane >> 2);
    const int c0b = n0 + wn * 64 + (lane & 3) * 2;
#pragma unroll
    for (int mm = 0; mm < 2; mm++)
#pragma unroll
        for (int nn = 0; nn < 8; nn++) {
            float* cc = acc[mm][nn];
            int col = c0b + nn * 8;
#pragma unroll
            for (int hf = 0; hf < 2; hf++) {
                int row = r0 + mm * 16 + hf * 8;
                float v0 = cc[hf * 2 + 0] + bias[col];
                float v1 = cc[hf * 2 + 1] + bias[col + 1];
                if (mode == 0) {
                    float2 o; o.x = v0; o.y = v1;
                    *(float2*)((float*)outp + (size_t)row * ldc + col) = o;
                } else {   // mode 3: transposed split (fused weight prep)
                    __nv_bfloat16* ob = (__nv_bfloat16*)outp;
                    __nv_bfloat16 h0 = __float2bfloat16(v0);
                    ob[(size_t)col * ldc + row] = h0;
                    ob[(size_t)col * ldc + oLo + row] =
                        __float2bfloat16(v0 - __bfloat162float(h0));
                    __nv_bfloat16 h1 = __float2bfloat16(v1);
                    ob[(size_t)(col + 1) * ldc + row] = h1;
                    ob[(size_t)(col + 1) * ldc + oLo + row] =
                        __float2bfloat16(v1 - __bfloat162float(h1));
                }
            }
        }
}

// ---------------------------------------------------------------------------
// 2-term GEMM: bf16 hi*hi + e4m3 cross terms (hi*lo + lo*hi) at k32.
// A : bf16 [M,lda] hi at col 0 ; A8: e4m3 [M,2048] hi at 0, lo*2^9 at 1024.
// Bt: bf16 [N,ldb] hi at col 0 ; B8: e4m3 [N,2048] hi*2^4 at 0, lo*2^13 at 1024.
// Cross acc carries 2^13; epilogue adds acc8 * 2^-13.   K = 1024 (32 chunks).
// mode 0: fp32 store ; mode 1: split-bf16 qkv scatter (s==0 scaled)
// ---------------------------------------------------------------------------
#define ST8 45056   // [A16 10240][B16 10240][A8h 6144][A8l 6144][B8h 6144][B8l 6144]
#define GEMM8_SMEM (3 * ST8)
#define DS8 1.220703125e-4f   // 2^-13

__global__ void __launch_bounds__(256, 1) gemm8(
    const __nv_bfloat16* __restrict__ A, int lda,
    const uint8_t* __restrict__ A8,
    const __nv_bfloat16* __restrict__ Bt, int ldb,
    const uint8_t* __restrict__ B8,
    const float* __restrict__ bias, void* __restrict__ outp,
    int ldc, int mode, float scale)
{
    extern __shared__ __align__(128) char smx[];
    const uint32_t su = smem_u32(smx);
    const int tid = threadIdx.x;
    const int warp = tid >> 5, lane = tid & 31;
    const int wm = warp >> 1, wn = warp & 1;
    const int m0 = blockIdx.y * 128, n0 = blockIdx.x * 128;

    float acc[2][8][4], acc8[2][8][4];
#pragma unroll
    for (int i = 0; i < 2; i++)
#pragma unroll
        for (int j = 0; j < 8; j++)
#pragma unroll
            for (int q = 0; q < 4; q++) { acc[i][j][q] = 0.f; acc8[i][j][q] = 0.f; }

    auto loads = [&](int c, int s) {
        uint32_t sa = su + (uint32_t)s * ST8;
        uint32_t sb = sa + 10240;
        uint32_t a8h = sa + 20480, a8l = a8h + 6144;
        uint32_t b8h = a8l + 6144, b8l = b8h + 6144;
        int k16 = c * 32;          // bf16 hi cols
        int k8 = c * 32;           // fp8 byte cols
#pragma unroll
        for (int j = 0; j < 2; j++) {
            int f = tid + j * 256;
            int r = f >> 2, si = (f & 3) * 16;
            cp16(sa + r * 80 + si,
                 (const char*)(A + (size_t)(m0 + r) * lda + k16) + si);
            cp16(sb + r * 80 + si,
                 (const char*)(Bt + (size_t)(n0 + r) * ldb + k16) + si);
        }
        {
            int r = tid >> 1, si = (tid & 1) * 16;
            cp16(a8h + r * 48 + si, A8 + (size_t)(m0 + r) * 2048 + k8 + si);
            cp16(a8l + r * 48 + si, A8 + (size_t)(m0 + r) * 2048 + 1024 + k8 + si);
            cp16(b8h + r * 48 + si, B8 + (size_t)(n0 + r) * 2048 + k8 + si);
            cp16(b8l + r * 48 + si, B8 + (size_t)(n0 + r) * 2048 + 1024 + k8 + si);
        }
        asm volatile("cp.async.commit_group;\n" ::: "memory");
    };

    loads(0, 0); loads(1, 1);
    int sc = 2;   // next stage slot

#pragma unroll 1
    for (int c = 0; c < 32; c++) {
        asm volatile("cp.async.wait_group 1;\n" ::: "memory");
        __syncthreads();
        if (c + 2 < 32) {
            loads(c + 2, sc);
            if (++sc == 3) sc = 0;
        }

        int s = c % 3;
        uint32_t sa = su + (uint32_t)s * ST8;
        uint32_t sb = sa + 10240;
        uint32_t a8hS = sa + 20480, a8lS = a8hS + 6144;
        uint32_t b8hS = a8lS + 6144, b8lS = b8hS + 6144;

        // bf16 hi*hi
#pragma unroll
        for (int kk = 0; kk < 2; kk++) {
            uint32_t af[2][4];
#pragma unroll
            for (int mm = 0; mm < 2; mm++) {
                uint32_t addr = sa +
                    (uint32_t)(wm * 32 + mm * 16 + (lane & 15)) * 80 +
                    ((lane >> 4) << 4) + kk * 32;
                ldm4(af[mm], addr);
            }
            uint32_t bf[4][4];
#pragma unroll
            for (int nb = 0; nb < 4; nb++) {
                int rown = wn * 64 + nb * 16 + ((lane >> 4) & 1) * 8 + (lane & 7);
                uint32_t addr = sb + (uint32_t)rown * 80 +
                    (((lane >> 3) & 1) << 4) + kk * 32;
                ldm4(bf[nb], addr);
            }
#pragma unroll
            for (int mm = 0; mm < 2; mm++)
#pragma unroll
                for (int nn = 0; nn < 8; nn++)
                    mma16816(acc[mm][nn], af[mm], &bf[nn >> 1][(nn & 1) * 2]);
        }

        // fp8 cross terms, k32
        {
            uint32_t a8h[2][4], a8l[2][4];
#pragma unroll
            for (int mm = 0; mm < 2; mm++) {
                uint32_t off = (uint32_t)(wm * 32 + mm * 16 + (lane & 15)) * 48 +
                               ((lane >> 4) << 4);
                ldm4(a8h[mm], a8hS + off);
                ldm4(a8l[mm], a8lS + off);
            }
#pragma unroll
            for (int j = 0; j < 8; j += 2) {
                int rowt = wn * 64 + (j + (lane >> 4)) * 8 + (lane & 7);
                uint32_t off = (uint32_t)rowt * 48 + (((lane >> 3) & 1) << 4);
                uint32_t th[4], tl[4];
                ldm4(th, b8hS + off);
                ldm4(tl, b8lS + off);
#pragma unroll
                for (int mm = 0; mm < 2; mm++) {
                    mma_fp8(acc8[mm][j],     a8h[mm], &tl[0]);
                    mma_fp8(acc8[mm][j],     a8l[mm], &th[0]);
                    mma_fp8(acc8[mm][j + 1], a8h[mm], &tl[2]);
                    mma_fp8(acc8[mm][j + 1], a8l[mm], &th[2]);
                }
            }
        }
    }

    const int r0 = m0 + wm * 32 + (lane >> 2);
    const int c0b = n0 + wn * 64 + (lane & 3) * 2;
#pragma unroll
    for (int mm = 0; mm < 2; mm++)
#pragma unroll
        for (int nn = 0; nn < 8; nn++) {
            float* cc = acc[mm][nn];
            float* c8 = acc8[mm][nn];
            int col = c0b + nn * 8;
#pragma unroll
            for (int hf = 0; hf < 2; hf++) {
                int row = r0 + mm * 16 + hf * 8;
                float v0 = cc[hf * 2 + 0] + c8[hf * 2 + 0] * DS8 + bias[col];
                float v1 = cc[hf * 2 + 1] + c8[hf * 2 + 1] * DS8 + bias[col + 1];
                if (mode == 0) {
                    float2 o; o.x = v0; o.y = v1;
                    *(float2*)((float*)outp + (size_t)row * ldc + col) = o;
                } else {   // mode 1: split-bf16 qkv scatter
                    int s = col >> 10;
                    int c1 = col & 1023;
                    int h = c1 >> 6, d = c1 & 63;
                    float sc2 = (s == 0) ? scale : 1.f;
                    v0 *= sc2; v1 *= sc2;
                    int bI = row >> 12, t = row & 4095;
                    __nv_bfloat16* ob = (__nv_bfloat16*)outp;
                    size_t rb = ((size_t)(s * 32 + bI * 16 + h) * T_ + t) * 128;
                    __nv_bfloat162 hv, lv;
                    hv.x = __float2bfloat16(v0);
                    hv.y = __float2bfloat16(v1);
                    lv.x = __float2bfloat16(v0 - __bfloat162float(hv.x));
                    lv.y = __float2bfloat16(v1 - __bfloat162float(hv.y));
                    *(__nv_bfloat162*)&ob[rb + d] = hv;
                    *(__nv_bfloat162*)&ob[rb + 64 + d] = lv;
                }
            }
        }
}

// ---------------------------------------------------------------------------
// Conversions
// ---------------------------------------------------------------------------
__global__ __launch_bounds__(256) void wsplitT(
    const float* __restrict__ W, int K, int N, __nv_bfloat16* __restrict__ Wt)
{
    __shared__ float tile[32][33];
    int n0 = blockIdx.x * 32, k0 = blockIdx.y * 32;
    int tx = threadIdx.x, ty = threadIdx.y;
#pragma unroll
    for (int i = 0; i < 32; i += 8)
        tile[ty + i][tx] = W[(size_t)(k0 + ty + i) * N + n0 + tx];
    __syncthreads();
#pragma unroll
    for (int i = 0; i < 32; i += 8) {
        int n = n0 + ty + i, k = k0 + tx;
        float v = tile[tx][ty + i];
        __nv_bfloat16 h = __float2bfloat16(v);
        Wt[(size_t)n * 2 * K + k] = h;
        Wt[(size_t)n * 2 * K + K + k] = __float2bfloat16(v - __bfloat162float(h));
    }
}

__global__ __launch_bounds__(256) void rowsplit(
    const float* __restrict__ W, int ldw, int colOff,
    __nv_bfloat16* __restrict__ out)
{
    int i = blockIdx.x;
    int c = threadIdx.x * 4;
    float4 v = *(const float4*)&W[(size_t)i * ldw + colOff + c];
    __nv_bfloat162 h0, h1, l0, l1;
    h0.x = __float2bfloat16(v.x); h0.y = __float2bfloat16(v.y);
    h1.x = __float2bfloat16(v.z); h1.y = __float2bfloat16(v.w);
    l0.x = __float2bfloat16(v.x - __bfloat162float(h0.x));
    l0.y = __float2bfloat16(v.y - __bfloat162float(h0.y));
    l1.x = __float2bfloat16(v.z - __bfloat162float(h1.x));
    l1.y = __float2bfloat16(v.w - __bfloat162float(h1.y));
    __nv_bfloat16* o = out + (size_t)i * 2048;
    *(__nv_bfloat162*)&o[c] = h0;
    *(__nv_bfloat162*)&o[c + 2] = h1;
    *(__nv_bfloat162*)&o[1024 + c] = l0;
    *(__nv_bfloat162*)&o[1024 + c + 2] = l1;
}

// x split -> bf16 split + e4m3 pair
__global__ __launch_bounds__(256) void xsplit(
    const float* __restrict__ x, __nv_bfloat16* __restrict__ xs,
    uint8_t* __restrict__ x8)
{
    size_t i = (size_t)blockIdx.x * 256 + threadIdx.x;
    size_t r = i >> 8;
    int c = (int)(i & 255) * 4;
    float4 v = *(const float4*)&x[r * 1024 + c];
    float hx = __bfloat162float(__float2bfloat16(v.x));
    float hy = __bfloat162float(__float2bfloat16(v.y));
    float hz = __bfloat162float(__float2bfloat16(v.z));
    float hw = __bfloat162float(__float2bfloat16(v.w));
    __nv_bfloat162 h0, h1, l0, l1;
    h0.x = __float2bfloat16(v.x); h0.y = __float2bfloat16(v.y);
    h1.x = __float2bfloat16(v.z); h1.y = __float2bfloat16(v.w);
    l0.x = __float2bfloat16(v.x - hx); l0.y = __float2bfloat16(v.y - hy);
    l1.x = __float2bfloat16(v.z - hz); l1.y = __float2bfloat16(v.w - hw);
    *(__nv_bfloat162*)&xs[r * 2048 + c] = h0;
    *(__nv_bfloat162*)&xs[r * 2048 + c + 2] = h1;
    *(__nv_bfloat162*)&xs[r * 2048 + 1024 + c] = l0;
    *(__nv_bfloat162*)&xs[r * 2048 + 1024 + c + 2] = l1;
    uchar4 qh, ql;
    qh.x = to_e4m3(hx); qh.y = to_e4m3(hy);
    qh.z = to_e4m3(hz); qh.w = to_e4m3(hw);
    ql.x = to_e4m3((v.x - hx) * 512.f); ql.y = to_e4m3((v.y - hy) * 512.f);
    ql.z = to_e4m3((v.z - hz) * 512.f); ql.w = to_e4m3((v.w - hw) * 512.f);
    *(uchar4*)&x8[r * 2048 + c] = qh;
    *(uchar4*)&x8[r * 2048 + 1024 + c] = ql;
}

// split-bf16 [rows][2048] -> e4m3 [rows][2048] with scales sh (hi), sl (lo)
__global__ __launch_bounds__(256) void tofp8(
    const __nv_bfloat16* __restrict__ Wt, float sh, float sl,
    uint8_t* __restrict__ W8)
{
    int row = blockIdx.x;
    int c = threadIdx.x * 4;
    const __nv_bfloat16* src = Wt + (size_t)row * 2048;
    uint8_t* dst = W8 + (size_t)row * 2048;
    uchar4 qh, ql;
    qh.x = to_e4m3(__bfloat162float(src[c + 0]) * sh);
    qh.y = to_e4m3(__bfloat162float(src[c + 1]) * sh);
    qh.z = to_e4m3(__bfloat162float(src[c + 2]) * sh);
    qh.w = to_e4m3(__bfloat162float(src[c + 3]) * sh);
    ql.x = to_e4m3(__bfloat162float(src[1024 + c + 0]) * sl);
    ql.y = to_e4m3(__bfloat162float(src[1024 + c + 1]) * sl);
    ql.z = to_e4m3(__bfloat162float(src[1024 + c + 2]) * sl);
    ql.w = to_e4m3(__bfloat162float(src[1024 + c + 3]) * sl);
    *(uchar4*)&dst[c] = qh;
    *(uchar4*)&dst[1024 + c] = ql;
}

__global__ __launch_bounds__(1024) void biasfold3(
    const float* __restrict__ bc,
    const float* __restrict__ Wq, const float* __restrict__ Wk,
    const float* __restrict__ Wv,
    const float* __restrict__ bq, const float* __restrict__ bk,
    const float* __restrict__ bv,
    float* __restrict__ out)
{
    int s = blockIdx.x;
    int n = threadIdx.x;
    const float* W  = (s == 0) ? Wq : (s == 1) ? Wk : Wv;
    const float* b2 = (s == 0) ? bq : (s == 1) ? bk : bv;
    const float* bs = bc + s * 1024;
    float a0 = 0.f, a1 = 0.f, a2 = 0.f, a3 = 0.f;
#pragma unroll 1
    for (int m = 0; m < 1024; m += 16) {
#pragma unroll
        for (int j = 0; j < 16; j++) {
            float w = W[(size_t)(m + j) * 1024 + n];
            float bb = bs[m + j];
            if ((j & 3) == 0) a0 = fmaf(bb, w, a0);
            else if ((j & 3) == 1) a1 = fmaf(bb, w, a1);
            else if ((j & 3) == 2) a2 = fmaf(bb, w, a2);
            else a3 = fmaf(bb, w, a3);
        }
    }
    out[s * 1024 + n] = a0 + a1 + a2 + a3 + b2[n];
}

// ---------------------------------------------------------------------------
// HMMA dilated attention (unchanged from R12 winner)
// ---------------------------------------------------------------------------
#define AP 272
#define ATTN2_SMEM (3 * 128 * AP)

__global__ void __launch_bounds__(256, 1) attn2(
    const __nv_bfloat16* __restrict__ qkvb,
    float* __restrict__ o0, float* __restrict__ l0,
    float* __restrict__ o1, float* __restrict__ l1,
    float* __restrict__ o2, float* __restrict__ l2)
{
    extern __shared__ __align__(128) char sm2[];
    const uint32_t Qs = smem_u32(sm2);
    const uint32_t Ks = Qs + 128 * AP;
    const uint32_t Vt = Ks + 128 * AP;

    const int tid = threadIdx.x;
    const int warp = tid >> 5, lane = tid & 31;
    const int m0 = (3 - blockIdx.x) * 128;
    const int y = blockIdx.y;
    int w, r, seg, Tr;
    float *obr, *lbr;
    if (y < 8)       { w = 512;  r = 1; seg = y;      Tr = 4096; obr = o0; lbr = l0; }
    else if (y < 12) { w = 1024; r = 2; seg = y - 8;  Tr = 2048; obr = o1; lbr = l1; }
    else             { w = 2048; r = 4; seg = y - 12; Tr = 1024; obr = o2; lbr = l2; }
    const int bh = blockIdx.z;
    const int h = bh & 15;
    const int off = h & (r - 1);
    const int segbase = seg * w + off;
    const __nv_bfloat16* qb = qkvb;
    const __nv_bfloat16* kb = qkvb + (size_t)32 * T_ * 128;
    const __nv_bfloat16* vb = qkvb + (size_t)64 * T_ * 128;
    const size_t bhbase = (size_t)bh * T_;

#pragma unroll
    for (int j = 0; j < 8; j++) {
        int f = tid + j * 256;
        int row = f >> 4, si = f & 15;
        const __nv_bfloat16* g =
            qb + (bhbase + segbase + (size_t)(m0 + row) * r) * 128 + si * 8;
        cp16(Qs + row * AP + si * 16, g);
    }
    asm volatile("cp.async.commit_group;\n" ::: "memory");

    float S[16][4];
    float O[8][4];
#pragma unroll
    for (int i = 0; i < 8; i++)
#pragma unroll
        for (int j2 = 0; j2 < 4; j2++) O[i][j2] = 0.f;
    float ml[2] = {-1e30f, -1e30f};
    float ll[2] = {0.f, 0.f};

    const int ntile = (m0 >> 7) + 1;
#pragma unroll 1
    for (int nt = 0; nt < ntile; nt++) {
        const int n0 = nt * 128;
        if (nt > 0) __syncthreads();

#pragma unroll
        for (int j = 0; j < 8; j++) {
            int f = tid + j * 256;
            int row = f >> 4, si = f & 15;
            const __nv_bfloat16* g =
                kb + (bhbase + segbase + (size_t)(n0 + row) * r) * 128 + si * 8;
            cp16(Ks + row * AP + si * 16, g);
        }
        asm volatile("cp.async.commit_group;\n" ::: "memory");

#pragma unroll
        for (int j = 0; j < 8; j++) {
            int f = tid + j * 256;
            int key = f & 127, si = f >> 7;
            const uint4 vv = *(const uint4*)(
                vb + (bhbase + segbase + (size_t)(n0 + key) * r) * 128 + si * 8);
            const uint16_t* pv = (const uint16_t*)&vv;
#pragma unroll
            for (int e = 0; e < 8; e++)
                asm volatile("st.shared.u16 [%0], %1;" ::
                             "r"(Vt + (si * 8 + e) * AP + key * 2), "h"(pv[e]));
        }
        asm volatile("cp.async.wait_group 0;\n" ::: "memory");
        __syncthreads();

#pragma unroll
        for (int t = 0; t < 16; t++)
#pragma unroll
            for (int j2 = 0; j2 < 4; j2++) S[t][j2] = 0.f;

#pragma unroll
        for (int kk = 0; kk < 4; kk++) {
            uint32_t qh[4], qlo[4];
            uint32_t abase = Qs + (uint32_t)(warp * 16 + (lane & 15)) * AP +
                             ((lane >> 4) << 4) + kk * 32;
            ldm4(qh, abase);
            ldm4(qlo, abase + 128);
#pragma unroll
            for (int hf = 0; hf < 2; hf++) {
                uint32_t kh[4][4], kl2[4][4];
#pragma unroll
                for (int nb = 0; nb < 4; nb++) {
                    int rowk = hf * 64 + nb * 16 + ((lane >> 4) & 1) * 8 + (lane & 7);
                    uint32_t kaddr = Ks + (uint32_t)rowk * AP +
                                     (((lane >> 3) & 1) << 4) + kk * 32;
                    ldm4(kh[nb], kaddr);
                    ldm4(kl2[nb], kaddr + 128);
                }
#pragma unroll
                for (int nn = 0; nn < 8; nn++) {
                    int t = hf * 8 + nn;
                    const uint32_t* bh2 = &kh[nn >> 1][(nn & 1) * 2];
                    const uint32_t* bl2 = &kl2[nn >> 1][(nn & 1) * 2];
                    mma16816(S[t], qh, bh2);
                    mma16816(S[t], qlo, bh2);
                    mma16816(S[t], qh, bl2);
                }
            }
        }

        if (n0 == m0) {
#pragma unroll
            for (int t = 0; t < 16; t++) {
                int colb = n0 + t * 8 + (lane & 3) * 2;
#pragma unroll
                for (int j2 = 0; j2 < 4; j2++) {
                    int rowg = m0 + warp * 16 + (lane >> 2) + (j2 >> 1) * 8;
                    if (colb + (j2 & 1) > rowg) S[t][j2] = -1e30f;
                }
            }
        }

#pragma unroll
        for (int rr = 0; rr < 2; rr++) {
            float vmax = -1e30f;
#pragma unroll
            for (int t = 0; t < 16; t++) {
                vmax = fmaxf(vmax, S[t][rr * 2 + 0]);
                vmax = fmaxf(vmax, S[t][rr * 2 + 1]);
            }
            vmax = fmaxf(vmax, __shfl_xor_sync(0xffffffffu, vmax, 1));
            vmax = fmaxf(vmax, __shfl_xor_sync(0xffffffffu, vmax, 2));
            float mn = fmaxf(ml[rr], vmax);
            float alpha = __expf(ml[rr] - mn);
            ml[rr] = mn;
            float rs = 0.f;
#pragma unroll
            for (int t = 0; t < 16; t++) {
                float e0 = fexp2((S[t][rr * 2 + 0] - mn) * 1.44269504f);
                float e1 = fexp2((S[t][rr * 2 + 1] - mn) * 1.44269504f);
                S[t][rr * 2 + 0] = e0;
                S[t][rr * 2 + 1] = e1;
                rs += e0 + e1;
            }
            rs += __shfl_xor_sync(0xffffffffu, rs, 1);
            rs += __shfl_xor_sync(0xffffffffu, rs, 2);
            ll[rr] = ll[rr] * alpha + rs;
#pragma unroll
            for (int nn = 0; nn < 8; nn++) {
                O[nn][rr * 2 + 0] *= alpha;
                O[nn][rr * 2 + 1] *= alpha;
            }
        }

#pragma unroll
        for (int ks = 0; ks < 8; ks++) {
            uint32_t ph[4], pl[4];
#pragma unroll
            for (int q2 = 0; q2 < 4; q2++) {
                int t = ks * 2 + (q2 >> 1);
                float a = S[t][(q2 & 1) * 2 + 0];
                float b = S[t][(q2 & 1) * 2 + 1];
                __nv_bfloat162 hv;
                hv.x = __float2bfloat16(a);
                hv.y = __float2bfloat16(b);
                ph[q2] = *(uint32_t*)&hv;
                __nv_bfloat162 lv;
                lv.x = __float2bfloat16(a - __bfloat162float(hv.x));
                lv.y = __float2bfloat16(b - __bfloat162float(hv.y));
                pl[q2] = *(uint32_t*)&lv;
            }
            uint32_t vh[4][4], vl2[4][4];
#pragma unroll
            for (int nb = 0; nb < 4; nb++) {
                int rowd = nb * 16 + ((lane >> 4) & 1) * 8 + (lane & 7);
                uint32_t vaddr = Vt + (uint32_t)rowd * AP +
                                 (((lane >> 3) & 1) << 4) + ks * 32;
                ldm4(vh[nb], vaddr);
                ldm4(vl2[nb], vaddr + 64 * AP);
            }
#pragma unroll
            for (int nn = 0; nn < 8; nn++) {
                const uint32_t* bh2 = &vh[nn >> 1][(nn & 1) * 2];
                const uint32_t* bl2 = &vl2[nn >> 1][(nn & 1) * 2];
                mma16816(O[nn], ph, bh2);
                mma16816(O[nn], pl, bh2);
                mma16816(O[nn], ph, bl2);
            }
        }
    }

#pragma unroll
    for (int rr = 0; rr < 2; rr++) {
        float inv = 1.f / ll[rr];
        size_t orow = (size_t)bh * Tr + seg * 512 + m0 + warp * 16 +
                      (lane >> 2) + rr * 8;
#pragma unroll
        for (int nn = 0; nn < 8; nn++) {
            float2 o2;
            o2.x = O[nn][rr * 2 + 0] * inv;
            o2.y = O[nn][rr * 2 + 1] * inv;
            *(float2*)&obr[orow * D_ + nn * 8 + (lane & 3) * 2] = o2;
        }
        if ((lane & 3) == 0) lbr[orow] = ml[rr] + logf(ll[rr]);
    }
}

// ---------------------------------------------------------------------------
// Combine; emit split bf16 y2 AND e4m3 y8
// ---------------------------------------------------------------------------
__global__ __launch_bounds__(128) void combine_kernel(
    const float* __restrict__ o0, const float* __restrict__ o1,
    const float* __restrict__ o2,
    const float* __restrict__ l0, const float* __restrict__ l1,
    const float* __restrict__ l2,
    __nv_bfloat16* __restrict__ y2, uint8_t* __restrict__ y8)
{
    int rowid = blockIdx.x * 128 + threadIdx.x;
    int bh = rowid >> 12;
    int t = rowid & 4095;
    int h = bh & (H_ - 1);
    int b = bh >> 4;

    float L0 = l0[(size_t)bh * 4096 + t];
    bool c1 = ((t & 1) == (h & 1));
    bool c2 = ((t & 3) == (h & 3));
    size_t i1 = (size_t)bh * 2048 + ((size_t)(t >> 10) << 9) + ((t & 1023) >> 1);
    size_t i2 = (size_t)bh * 1024 + ((size_t)(t >> 11) << 9) + ((t & 2047) >> 2);
    float L1 = c1 ? l1[i1] : -1e30f;
    float L2 = c2 ? l2[i2] : -1e30f;
    float m = fmaxf(L0, fmaxf(L1, L2));
    float w0 = __expf(L0 - m);
    float w1 = c1 ? __expf(L1 - m) : 0.f;
    float w2 = c2 ? __expf(L2 - m) : 0.f;
    float inv = 1.f / (w0 + w1 + w2);
    w0 *= inv; w1 *= inv; w2 *= inv;

    const float* p0 = o0 + ((size_t)bh * 4096 + t) * D_;
    const float* p1 = o1 + i1 * D_;
    const float* p2 = o2 + i2 * D_;
    size_t ybase = (size_t)(b * 4096 + t) * 2048 + h * D_;

#pragma unroll
    for (int d = 0; d < 64; d += 4) {
        float4 a0 = *(const float4*)&p0[d];
        float4 res = make_float4(w0 * a0.x, w0 * a0.y, w0 * a0.z, w0 * a0.w);
        if (c1) {
            float4 a1 = *(const float4*)&p1[d];
            res.x += w1 * a1.x; res.y += w1 * a1.y;
            res.z += w1 * a1.z; res.w += w1 * a1.w;
        }
        if (c2) {
            float4 a2 = *(const float4*)&p2[d];
            res.x += w2 * a2.x; res.y += w2 * a2.y;
            res.z += w2 * a2.z; res.w += w2 * a2.w;
        }
        float hx = __bfloat162float(__float2bfloat16(res.x));
        float hy = __bfloat162float(__float2bfloat16(res.y));
        float hz = __bfloat162float(__float2bfloat16(res.z));
        float hw = __bfloat162float(__float2bfloat16(res.w));
        __nv_bfloat162 h0, h1, lo0, lo1;
        h0.x = __float2bfloat16(res.x); h0.y = __float2bfloat16(res.y);
        h1.x = __float2bfloat16(res.z); h1.y = __float2bfloat16(res.w);
        lo0.x = __float2bfloat16(res.x - hx); lo0.y = __float2bfloat16(res.y - hy);
        lo1.x = __float2bfloat16(res.z - hz); lo1.y = __float2bfloat16(res.w - hw);
        *(__nv_bfloat162*)&y2[ybase + d] = h0;
        *(__nv_bfloat162*)&y2[ybase + d + 2] = h1;
        *(__nv_bfloat162*)&y2[ybase + 1024 + d] = lo0;
        *(__nv_bfloat162*)&y2[ybase + 1024 + d + 2] = lo1;
        uchar4 qh, ql;
        qh.x = to_e4m3(hx); qh.y = to_e4m3(hy);
        qh.z = to_e4m3(hz); qh.w = to_e4m3(hw);
        ql.x = to_e4m3((res.x - hx) * 512.f);
        ql.y = to_e4m3((res.y - hy) * 512.f);
        ql.z = to_e4m3((res.z - hz) * 512.f);
        ql.w = to_e4m3((res.w - hw) * 512.f);
        *(uchar4*)&y8[ybase + d] = qh;
        *(uchar4*)&y8[ybase + 1024 + d] = ql;
    }
}

// ---------------------------------------------------------------------------
// Launch
// ---------------------------------------------------------------------------
extern "C" void kernel_launch(void* const* d_in, const int* in_sizes, int n_in,
                              void* d_out, int out_size)
{
    (void)in_sizes; (void)n_in; (void)out_size;
    const float* x        = (const float*)d_in[0];
    const float* c_attn_w = (const float*)d_in[1];
    const float* c_attn_b = (const float*)d_in[2];
    const float* q_w      = (const float*)d_in[3];
    const float* q_b      = (const float*)d_in[4];
    const float* k_w      = (const float*)d_in[5];
    const float* k_b      = (const float*)d_in[6];
    const float* v_w      = (const float*)d_in[7];
    const float* v_b      = (const float*)d_in[8];
    const float* o_w      = (const float*)d_in[9];
    const float* o_b      = (const float*)d_in[10];
    float* out = (float*)d_out;

    __nv_bfloat16 *xs, *wqkv, *wo, *wcr, *wf, *y2, *qkvb;
    uint8_t *x8, *wf8, *wo8, *y8;
    float *bf, *zero, *o0, *o1, *o2, *l0, *l1, *l2;
    cudaGetSymbolAddress((void**)&xs,   g_xs);
    cudaGetSymbolAddress((void**)&x8,   g_x8);
    cudaGetSymbolAddress((void**)&wqkv, g_wqkv);
    cudaGetSymbolAddress((void**)&wo,   g_wo);
    cudaGetSymbolAddress((void**)&wo8,  g_wo8);
    cudaGetSymbolAddress((void**)&wcr,  g_wcr);
    cudaGetSymbolAddress((void**)&wf,   g_wf);
    cudaGetSymbolAddress((void**)&wf8,  g_wf8);
    cudaGetSymbolAddress((void**)&bf,   g_bf);
    cudaGetSymbolAddress((void**)&zero, g_zero);
    cudaGetSymbolAddress((void**)&qkvb, g_qkvb);
    cudaGetSymbolAddress((void**)&y2,   g_y2);
    cudaGetSymbolAddress((void**)&y8,   g_y8);
    cudaGetSymbolAddress((void**)&o0,   g_o0);
    cudaGetSymbolAddress((void**)&o1,   g_o1);
    cudaGetSymbolAddress((void**)&o2,   g_o2);
    cudaGetSymbolAddress((void**)&l0,   g_l0);
    cudaGetSymbolAddress((void**)&l1,   g_l1);
    cudaGetSymbolAddress((void**)&l2,   g_l2);

    cudaFuncSetAttribute(gemm_mma, cudaFuncAttributeMaxDynamicSharedMemorySize,
                         GEMM_SMEM);
    cudaFuncSetAttribute(gemm8, cudaFuncAttributeMaxDynamicSharedMemorySize,
                         GEMM8_SMEM);
    cudaFuncSetAttribute(attn2, cudaFuncAttributeMaxDynamicSharedMemorySize,
                         ATTN2_SMEM);

    const size_t WSL = (size_t)1024 * 2048 * sizeof(__nv_bfloat16);  // 4 MB

    // 0) conversions
    xsplit<<<8192, 256>>>(x, xs, x8);
    wsplitT<<<dim3(32, 32), dim3(32, 8)>>>(q_w, 1024, 1024, wqkv);
    wsplitT<<<dim3(32, 32), dim3(32, 8)>>>(k_w, 1024, 1024,
                                           wqkv + (size_t)1024 * 2048);
    wsplitT<<<dim3(32, 32), dim3(32, 8)>>>(v_w, 1024, 1024,
                                           wqkv + (size_t)2048 * 2048);
    wsplitT<<<dim3(32, 32), dim3(32, 8)>>>(o_w, 1024, 1024, wo);
    rowsplit<<<1024, 256>>>(c_attn_w, 3072, 0,    wcr);
    rowsplit<<<1024, 256>>>(c_attn_w, 3072, 1024, wcr + (size_t)1024 * 2048);
    rowsplit<<<1024, 256>>>(c_attn_w, 3072, 2048, wcr + (size_t)2048 * 2048);
    biasfold3<<<3, 1024>>>(c_attn_b, q_w, k_w, v_w, q_b, k_b, v_b, bf);
    tofp8<<<1024, 256>>>(wo, 16.f, 8192.f, wo8);

    // 1) fused-weight prep (z-batched, 3-term bf16)
    gemm_mma<<<dim3(8, 8, 3), 256, GEMM_SMEM>>>(
        wcr, 2048, 0, 1024, wqkv, 2048, 0, 1024,
        zero, wf, 2048, 1024, 32, 3, 1.f, WSL, WSL, WSL);
    tofp8<<<3072, 256>>>(wf, 16.f, 8192.f, wf8);

    // 2) merged projection (bf16 + fp8 cross): q/k/v -> split bf16
    gemm8<<<dim3(24, 64), 256, GEMM8_SMEM>>>(
        xs, 2048, x8, wf, 2048, wf8, bf, qkvb, 0, 1, 0.125f);

    // 3) HMMA dilated attention, all branches in one launch
    attn2<<<dim3(4, 14, 32), 256, ATTN2_SMEM>>>(qkvb, o0, l0, o1, l1, o2, l2);

    // 4) combine -> split bf16 y2 + e4m3 y8
    combine_kernel<<<dim3(B_ * H_ * T_ / 128), 128>>>(o0, o1, o2, l0, l1, l2,
                                                      y2, y8);
    // 5) out = y @ o_w + o_b  (bf16 + fp8 cross)
    gemm8<<<dim3(8, 64), 256, GEMM8_SMEM>>>(
        y2, 2048, y8, wo, 2048, wo8, o_b, out, 1024, 0, 1.f);
}

// round 16
// speedup vs baseline: 1.2258x; 1.2258x over previous
#include <cuda_runtime.h>
#include <cuda_bf16.h>
#include <cstdint>

// Problem constants
#define B_   2
#define T_   4096
#define C_   1024
#define H_   16
#define D_   64
#define NTOK 8192   // B_*T_

// ---------------------------------------------------------------------------
// Scratch (static device globals; no runtime allocation allowed)
// ---------------------------------------------------------------------------
__device__ __nv_bfloat16 g_xs  [(size_t)NTOK * 2048];   // x split [hi|lo]
__device__ __nv_bfloat16 g_wqkv[(size_t)3 * 1024 * 2048]; // Wq/Wk/Wv^T split
__device__ __nv_bfloat16 g_wo  [(size_t)1024 * 2048];
__device__ __nv_bfloat16 g_wcr [(size_t)3 * 1024 * 2048]; // Wc slices row-split
__device__ __nv_bfloat16 g_wf  [(size_t)3072 * 2048];   // fused W^T split [n,2k]
__device__ float g_bf[3072];                            // fused biases
__device__ float g_zero[1024];                          // zero bias (static 0)
// q/k/v as split bf16: [s][bh][t][128] rows = hi(64) | lo(64)
__device__ __nv_bfloat16 g_qkvb[(size_t)3 * 32 * T_ * 128];
__device__ float g_o0[(size_t)B_ * H_ * T_ * D_];
__device__ float g_o1[(size_t)B_ * H_ * (T_ / 2) * D_];
__device__ float g_o2[(size_t)B_ * H_ * (T_ / 4) * D_];
__device__ float g_l0[B_ * H_ * T_];
__device__ float g_l1[B_ * H_ * (T_ / 2)];
__device__ float g_l2[B_ * H_ * (T_ / 4)];
__device__ __nv_bfloat16 g_y2[(size_t)NTOK * 2048];     // combined split [hi|lo]

// ---------------------------------------------------------------------------
// PTX helpers (base sm_103 target: mma.sync / ldmatrix / cp.async only)
// ---------------------------------------------------------------------------
__device__ __forceinline__ uint32_t smem_u32(const void* p) {
    uint32_t a;
    asm("{ .reg .u64 t; cvta.to.shared.u64 t, %1; cvt.u32.u64 %0, t; }"
        : "=r"(a) : "l"(p));
    return a;
}
__device__ __forceinline__ void cp16(uint32_t dst, const void* src) {
    asm volatile("cp.async.cg.shared.global [%0], [%1], 16;\n"
                 :: "r"(dst), "l"(src));
}
__device__ __forceinline__ void ldm4(uint32_t* r, uint32_t a) {
    asm volatile("ldmatrix.sync.aligned.m8n8.x4.shared.b16 {%0,%1,%2,%3}, [%4];"
                 : "=r"(r[0]), "=r"(r[1]), "=r"(r[2]), "=r"(r[3]) : "r"(a));
}
__device__ __forceinline__ void ldm4t(uint32_t* r, uint32_t a) {
    asm volatile("ldmatrix.sync.aligned.m8n8.x4.trans.shared.b16 {%0,%1,%2,%3}, [%4];"
                 : "=r"(r[0]), "=r"(r[1]), "=r"(r[2]), "=r"(r[3]) : "r"(a));
}
__device__ __forceinline__ void mma16816(float* c, const uint32_t* a,
                                         const uint32_t* b) {
    asm volatile(
        "mma.sync.aligned.m16n8k16.row.col.f32.bf16.bf16.f32 "
        "{%0,%1,%2,%3}, {%4,%5,%6,%7}, {%8,%9}, {%0,%1,%2,%3};"
        : "+f"(c[0]), "+f"(c[1]), "+f"(c[2]), "+f"(c[3])
        : "r"(a[0]), "r"(a[1]), "r"(a[2]), "r"(a[3]), "r"(b[0]), "r"(b[1]));
}
// exp2 on the FMA pipe (degree-5 minimax on [0,1) + exponent-bit scale)
__device__ __forceinline__ float fexp2(float t) {
    t = fmaxf(t, -80.f);
    float fl = floorf(t);
    float f = t - fl;
    float p = 0.0013276471f;
    p = fmaf(p, f, 0.0096788383f);
    p = fmaf(p, f, 0.0555072548f);
    p = fmaf(p, f, 0.2402211502f);
    p = fmaf(p, f, 0.6931469902f);
    p = fmaf(p, f, 1.0f);
    int e = (int)fl;
    return p * __int_as_float((e + 127) << 23);
}

// ---------------------------------------------------------------------------
// Split-bf16 HMMA GEMM. grid.z batching via byte strides zbA/zbB/zbO.
// mode 0: fp32 store out[row*ldc + n]
// mode 1: split-bf16 qkv scatter to [s][bh][t][hi64|lo64]; s==0 scaled
// mode 3: transposed split store (fused-weight prep)
// ---------------------------------------------------------------------------
#define STAGEB 20480
#define GEMM_SMEM (4 * STAGEB)

__global__ __launch_bounds__(256) void gemm_mma(
    const __nv_bfloat16* __restrict__ A0, int lda, int aHi, int aLo,
    const __nv_bfloat16* __restrict__ Bt0, int ldb, int bHi, int bLo,
    const float* __restrict__ bias, void* __restrict__ outp0,
    int ldc, int oLo, int NKC, int mode, float scale,
    size_t zbA, size_t zbB, size_t zbO)
{
    const __nv_bfloat16* A =
        (const __nv_bfloat16*)((const char*)A0 + (size_t)blockIdx.z * zbA);
    const __nv_bfloat16* Bt =
        (const __nv_bfloat16*)((const char*)Bt0 + (size_t)blockIdx.z * zbB);
    void* outp = (char*)outp0 + (size_t)blockIdx.z * zbO;

    extern __shared__ __align__(128) char smx[];
    const uint32_t su = smem_u32(smx);
    const int tid = threadIdx.x;
    const int warp = tid >> 5, lane = tid & 31;
    const int wm = warp >> 1, wn = warp & 1;
    const int m0 = blockIdx.y * 128, n0 = blockIdx.x * 128;
    const int NC = 3 * NKC;

    float acc[2][8][4];
#pragma unroll
    for (int i = 0; i < 2; i++)
#pragma unroll
        for (int j = 0; j < 8; j++)
#pragma unroll
            for (int q = 0; q < 4; q++) acc[i][j][q] = 0.f;

    auto loads = [&](int c, int s) {
        int ka, kb;
        if (c < NKC)            { ka = aHi + c * 32;            kb = bHi + c * 32; }
        else if (c < 2 * NKC)   { int k2 = c - NKC;     ka = aHi + k2 * 32; kb = bLo + k2 * 32; }
        else                    { int k2 = c - 2 * NKC; ka = aLo + k2 * 32; kb = bHi + k2 * 32; }
        uint32_t sa = su + (uint32_t)s * STAGEB;
        uint32_t sb = sa + 10240;
#pragma unroll
        for (int j = 0; j < 2; j++) {
            int f = tid + j * 256;
            int r = f >> 2, si = (f & 3) * 16;
            cp16(sa + r * 80 + si,
                 (const char*)(A + (size_t)(m0 + r) * lda + ka) + si);
            cp16(sb + r * 80 + si,
                 (const char*)(Bt + (size_t)(n0 + r) * ldb + kb) + si);
        }
        asm volatile("cp.async.commit_group;\n" ::: "memory");
    };

    loads(0, 0); loads(1, 1); loads(2, 2);

#pragma unroll 1
    for (int c = 0; c < NC; c++) {
        asm volatile("cp.async.wait_group %0;\n" :: "n"(2) : "memory");
        __syncthreads();
        if (c + 3 < NC) loads(c + 3, (c + 3) & 3);

        uint32_t sa = su + (uint32_t)(c & 3) * STAGEB;
        uint32_t sb = sa + 10240;
#pragma unroll
        for (int kk = 0; kk < 2; kk++) {
            uint32_t af[2][4];
#pragma unroll
            for (int mm = 0; mm < 2; mm++) {
                uint32_t addr = sa +
                    (uint32_t)(wm * 32 + mm * 16 + (lane & 15)) * 80 +
                    ((lane >> 4) << 4) + kk * 32;
                ldm4(af[mm], addr);
            }
            uint32_t bf[4][4];
#pragma unroll
            for (int nb = 0; nb < 4; nb++) {
                int rown = wn * 64 + nb * 16 + ((lane >> 4) & 1) * 8 + (lane & 7);
                uint32_t addr = sb + (uint32_t)rown * 80 +
                    (((lane >> 3) & 1) << 4) + kk * 32;
                ldm4(bf[nb], addr);
            }
#pragma unroll
            for (int mm = 0; mm < 2; mm++)
#pragma unroll
                for (int nn = 0; nn < 8; nn++)
                    mma16816(acc[mm][nn], af[mm], &bf[nn >> 1][(nn & 1) * 2]);
        }
    }

    const int r0 = m0 + wm * 32 + (lane >> 2);
    const int c0b = n0 + wn * 64 + (lane & 3) * 2;
#pragma unroll
    for (int mm = 0; mm < 2; mm++)
#pragma unroll
        for (int nn = 0; nn < 8; nn++) {
            float* cc = acc[mm][nn];
            int col = c0b + nn * 8;
#pragma unroll
            for (int hf = 0; hf < 2; hf++) {
                int row = r0 + mm * 16 + hf * 8;
                float v0 = cc[hf * 2 + 0] + bias[col];
                float v1 = cc[hf * 2 + 1] + bias[col + 1];
                if (mode == 0) {
                    float2 o; o.x = v0; o.y = v1;
                    *(float2*)((float*)outp + (size_t)row * ldc + col) = o;
                } else if (mode == 1) {
                    int s = col >> 10;
                    int c1 = col & 1023;
                    int h = c1 >> 6, d = c1 & 63;
                    float sc = (s == 0) ? scale : 1.f;
                    v0 *= sc; v1 *= sc;
                    int bI = row >> 12, t = row & 4095;
                    __nv_bfloat16* ob = (__nv_bfloat16*)outp;
                    size_t rb = ((size_t)(s * 32 + bI * 16 + h) * T_ + t) * 128;
                    __nv_bfloat162 hv, lv;
                    hv.x = __float2bfloat16(v0);
                    hv.y = __float2bfloat16(v1);
                    lv.x = __float2bfloat16(v0 - __bfloat162float(hv.x));
                    lv.y = __float2bfloat16(v1 - __bfloat162float(hv.y));
                    *(__nv_bfloat162*)&ob[rb + d] = hv;
                    *(__nv_bfloat162*)&ob[rb + 64 + d] = lv;
                } else {   // mode 3: transposed split (fused weight prep)
                    __nv_bfloat16* ob = (__nv_bfloat16*)outp;
                    __nv_bfloat16 h0 = __float2bfloat16(v0);
                    ob[(size_t)col * ldc + row] = h0;
                    ob[(size_t)col * ldc + oLo + row] =
                        __float2bfloat16(v0 - __bfloat162float(h0));
                    __nv_bfloat16 h1 = __float2bfloat16(v1);
                    ob[(size_t)(col + 1) * ldc + row] = h1;
                    ob[(size_t)(col + 1) * ldc + oLo + row] =
                        __float2bfloat16(v1 - __bfloat162float(h1));
                }
            }
        }
}

// ---------------------------------------------------------------------------
// Conversions (z-batched)
// ---------------------------------------------------------------------------
__global__ __launch_bounds__(256) void wsplitT4(
    const float* __restrict__ q_w, const float* __restrict__ k_w,
    const float* __restrict__ v_w, const float* __restrict__ o_w,
    __nv_bfloat16* __restrict__ wqkv, __nv_bfloat16* __restrict__ wo)
{
    __shared__ float tile[32][33];
    const int z = blockIdx.z;
    const float* W = (z == 0) ? q_w : (z == 1) ? k_w : (z == 2) ? v_w : o_w;
    __nv_bfloat16* Wt = (z == 3) ? wo : wqkv + (size_t)z * 1024 * 2048;
    int n0 = blockIdx.x * 32, k0 = blockIdx.y * 32;
    int tx = threadIdx.x, ty = threadIdx.y;
#pragma unroll
    for (int i = 0; i < 32; i += 8)
        tile[ty + i][tx] = W[(size_t)(k0 + ty + i) * 1024 + n0 + tx];
    __syncthreads();
#pragma unroll
    for (int i = 0; i < 32; i += 8) {
        int n = n0 + ty + i, k = k0 + tx;
        float v = tile[tx][ty + i];
        __nv_bfloat16 h = __float2bfloat16(v);
        Wt[(size_t)n * 2048 + k] = h;
        Wt[(size_t)n * 2048 + 1024 + k] =
            __float2bfloat16(v - __bfloat162float(h));
    }
}

// Row-major split of c_attn_w slices: y = slice index (colOff = y*1024)
__global__ __launch_bounds__(256) void rowsplit3(
    const float* __restrict__ W, __nv_bfloat16* __restrict__ out)
{
    int i = blockIdx.x;
    int slice = blockIdx.y;
    int c = threadIdx.x * 4;
    float4 v = *(const float4*)&W[(size_t)i * 3072 + slice * 1024 + c];
    __nv_bfloat162 h0, h1, l0, l1;
    h0.x = __float2bfloat16(v.x); h0.y = __float2bfloat16(v.y);
    h1.x = __float2bfloat16(v.z); h1.y = __float2bfloat16(v.w);
    l0.x = __float2bfloat16(v.x - __bfloat162float(h0.x));
    l0.y = __float2bfloat16(v.y - __bfloat162float(h0.y));
    l1.x = __float2bfloat16(v.z - __bfloat162float(h1.x));
    l1.y = __float2bfloat16(v.w - __bfloat162float(h1.y));
    __nv_bfloat16* o = out + (size_t)slice * 1024 * 2048 + (size_t)i * 2048;
    *(__nv_bfloat162*)&o[c] = h0;
    *(__nv_bfloat162*)&o[c + 2] = h1;
    *(__nv_bfloat162*)&o[1024 + c] = l0;
    *(__nv_bfloat162*)&o[1024 + c + 2] = l1;
}

__global__ __launch_bounds__(256) void xsplit(
    const float* __restrict__ x, __nv_bfloat16* __restrict__ xs)
{
    size_t i = (size_t)blockIdx.x * 256 + threadIdx.x;
    size_t r = i >> 8;
    int c = (int)(i & 255) * 4;
    float4 v = *(const float4*)&x[r * 1024 + c];
    __nv_bfloat162 h0, h1, l0, l1;
    h0.x = __float2bfloat16(v.x); h0.y = __float2bfloat16(v.y);
    h1.x = __float2bfloat16(v.z); h1.y = __float2bfloat16(v.w);
    l0.x = __float2bfloat16(v.x - __bfloat162float(h0.x));
    l0.y = __float2bfloat16(v.y - __bfloat162float(h0.y));
    l1.x = __float2bfloat16(v.z - __bfloat162float(h1.x));
    l1.y = __float2bfloat16(v.w - __bfloat162float(h1.y));
    *(__nv_bfloat162*)&xs[r * 2048 + c] = h0;
    *(__nv_bfloat162*)&xs[r * 2048 + c + 2] = h1;
    *(__nv_bfloat162*)&xs[r * 2048 + 1024 + c] = l0;
    *(__nv_bfloat162*)&xs[r * 2048 + 1024 + c + 2] = l1;
}

__global__ __launch_bounds__(1024) void biasfold3(
    const float* __restrict__ bc,
    const float* __restrict__ Wq, const float* __restrict__ Wk,
    const float* __restrict__ Wv,
    const float* __restrict__ bq, const float* __restrict__ bk,
    const float* __restrict__ bv,
    float* __restrict__ out)
{
    int s = blockIdx.x;
    int n = threadIdx.x;
    const float* W  = (s == 0) ? Wq : (s == 1) ? Wk : Wv;
    const float* b2 = (s == 0) ? bq : (s == 1) ? bk : bv;
    const float* bs = bc + s * 1024;
    float a0 = 0.f, a1 = 0.f, a2 = 0.f, a3 = 0.f;
#pragma unroll 1
    for (int m = 0; m < 1024; m += 16) {
#pragma unroll
        for (int j = 0; j < 16; j++) {
            float w = W[(size_t)(m + j) * 1024 + n];
            float bb = bs[m + j];
            if ((j & 3) == 0) a0 = fmaf(bb, w, a0);
            else if ((j & 3) == 1) a1 = fmaf(bb, w, a1);
            else if ((j & 3) == 2) a2 = fmaf(bb, w, a2);
            else a3 = fmaf(bb, w, a3);
        }
    }
    out[s * 1024 + n] = a0 + a1 + a2 + a3 + b2[n];
}

// ---------------------------------------------------------------------------
// HMMA dilated attention, ALL branches in one launch.
// grid (4, 14, 32): y<8 branch0, y<12 branch1, else branch2.
// V now loaded row-major via cp.async; PV B-fragments via ldmatrix.x4.trans
// (no scalar transpose). Arithmetic identical to R12.
// ---------------------------------------------------------------------------
#define AP 272
#define ATTN2_SMEM (3 * 128 * AP)   // 104448 B

__global__ void __launch_bounds__(256, 1) attn2(
    const __nv_bfloat16* __restrict__ qkvb,
    float* __restrict__ o0, float* __restrict__ l0,
    float* __restrict__ o1, float* __restrict__ l1,
    float* __restrict__ o2, float* __restrict__ l2)
{
    extern __shared__ __align__(128) char sm2[];
    const uint32_t Qs = smem_u32(sm2);
    const uint32_t Ks = Qs + 128 * AP;
    const uint32_t Vs = Ks + 128 * AP;   // V rows: [key][hi64|lo64], pitch AP

    const int tid = threadIdx.x;
    const int warp = tid >> 5, lane = tid & 31;
    const int m0 = (3 - blockIdx.x) * 128;   // heavy tiles first
    const int y = blockIdx.y;
    int w, r, seg, Tr;
    float *obr, *lbr;
    if (y < 8)       { w = 512;  r = 1; seg = y;      Tr = 4096; obr = o0; lbr = l0; }
    else if (y < 12) { w = 1024; r = 2; seg = y - 8;  Tr = 2048; obr = o1; lbr = l1; }
    else             { w = 2048; r = 4; seg = y - 12; Tr = 1024; obr = o2; lbr = l2; }
    const int bh = blockIdx.z;
    const int h = bh & 15;
    const int off = h & (r - 1);
    const int segbase = seg * w + off;
    const __nv_bfloat16* qb = qkvb;
    const __nv_bfloat16* kb = qkvb + (size_t)32 * T_ * 128;
    const __nv_bfloat16* vb = qkvb + (size_t)64 * T_ * 128;
    const size_t bhbase = (size_t)bh * T_;

    // Q tile (once)
#pragma unroll
    for (int j = 0; j < 8; j++) {
        int f = tid + j * 256;
        int row = f >> 4, si = f & 15;
        const __nv_bfloat16* g =
            qb + (bhbase + segbase + (size_t)(m0 + row) * r) * 128 + si * 8;
        cp16(Qs + row * AP + si * 16, g);
    }
    asm volatile("cp.async.commit_group;\n" ::: "memory");

    float S[16][4];
    float O[8][4];
#pragma unroll
    for (int i = 0; i < 8; i++)
#pragma unroll
        for (int j2 = 0; j2 < 4; j2++) O[i][j2] = 0.f;
    float ml[2] = {-1e30f, -1e30f};
    float ll[2] = {0.f, 0.f};

    const int ntile = (m0 >> 7) + 1;
#pragma unroll 1
    for (int nt = 0; nt < ntile; nt++) {
        const int n0 = nt * 128;
        if (nt > 0) __syncthreads();

        // K + V tiles (both cp.async, one group)
#pragma unroll
        for (int j = 0; j < 8; j++) {
            int f = tid + j * 256;
            int row = f >> 4, si = f & 15;
            size_t gidx =
                (bhbase + segbase + (size_t)(n0 + row) * r) * 128 + si * 8;
            cp16(Ks + row * AP + si * 16, kb + gidx);
            cp16(Vs + row * AP + si * 16, vb + gidx);
        }
        asm volatile("cp.async.commit_group;\n" ::: "memory");
        asm volatile("cp.async.wait_group 0;\n" ::: "memory");
        __syncthreads();

        // ---- S = Q K^T, 3-term split ----
#pragma unroll
        for (int t = 0; t < 16; t++)
#pragma unroll
            for (int j2 = 0; j2 < 4; j2++) S[t][j2] = 0.f;

#pragma unroll
        for (int kk = 0; kk < 4; kk++) {
            uint32_t qh[4], qlo[4];
            uint32_t abase = Qs + (uint32_t)(warp * 16 + (lane & 15)) * AP +
                             ((lane >> 4) << 4) + kk * 32;
            ldm4(qh, abase);
            ldm4(qlo, abase + 128);
#pragma unroll
            for (int hf = 0; hf < 2; hf++) {
                uint32_t kh[4][4], kl2[4][4];
#pragma unroll
                for (int nb = 0; nb < 4; nb++) {
                    int rowk = hf * 64 + nb * 16 + ((lane >> 4) & 1) * 8 + (lane & 7);
                    uint32_t kaddr = Ks + (uint32_t)rowk * AP +
                                     (((lane >> 3) & 1) << 4) + kk * 32;
                    ldm4(kh[nb], kaddr);
                    ldm4(kl2[nb], kaddr + 128);
                }
#pragma unroll
                for (int nn = 0; nn < 8; nn++) {
                    int t = hf * 8 + nn;
                    const uint32_t* bh2 = &kh[nn >> 1][(nn & 1) * 2];
                    const uint32_t* bl2 = &kl2[nn >> 1][(nn & 1) * 2];
                    mma16816(S[t], qh, bh2);
                    mma16816(S[t], qlo, bh2);
                    mma16816(S[t], qh, bl2);
                }
            }
        }

        // Causal mask on the diagonal tile
        if (n0 == m0) {
#pragma unroll
            for (int t = 0; t < 16; t++) {
                int colb = n0 + t * 8 + (lane & 3) * 2;
#pragma unroll
                for (int j2 = 0; j2 < 4; j2++) {
                    int rowg = m0 + warp * 16 + (lane >> 2) + (j2 >> 1) * 8;
                    if (colb + (j2 & 1) > rowg) S[t][j2] = -1e30f;
                }
            }
        }

        // Online softmax (warp-local rows; quad shuffle reduce)
#pragma unroll
        for (int rr = 0; rr < 2; rr++) {
            float vmax = -1e30f;
#pragma unroll
            for (int t = 0; t < 16; t++) {
                vmax = fmaxf(vmax, S[t][rr * 2 + 0]);
                vmax = fmaxf(vmax, S[t][rr * 2 + 1]);
            }
            vmax = fmaxf(vmax, __shfl_xor_sync(0xffffffffu, vmax, 1));
            vmax = fmaxf(vmax, __shfl_xor_sync(0xffffffffu, vmax, 2));
            float mn = fmaxf(ml[rr], vmax);
            float alpha = __expf(ml[rr] - mn);
            ml[rr] = mn;
            float rs = 0.f;
#pragma unroll
            for (int t = 0; t < 16; t++) {
                float e0 = fexp2((S[t][rr * 2 + 0] - mn) * 1.44269504f);
                float e1 = fexp2((S[t][rr * 2 + 1] - mn) * 1.44269504f);
                S[t][rr * 2 + 0] = e0;
                S[t][rr * 2 + 1] = e1;
                rs += e0 + e1;
            }
            rs += __shfl_xor_sync(0xffffffffu, rs, 1);
            rs += __shfl_xor_sync(0xffffffffu, rs, 2);
            ll[rr] = ll[rr] * alpha + rs;
#pragma unroll
            for (int nn = 0; nn < 8; nn++) {
                O[nn][rr * 2 + 0] *= alpha;
                O[nn][rr * 2 + 1] *= alpha;
            }
        }

        // ---- O += P V, 3-term split; V fragments via ldmatrix.trans ----
#pragma unroll
        for (int ks = 0; ks < 8; ks++) {
            uint32_t ph[4], pl[4];
#pragma unroll
            for (int q2 = 0; q2 < 4; q2++) {
                int t = ks * 2 + (q2 >> 1);
                float a = S[t][(q2 & 1) * 2 + 0];
                float b = S[t][(q2 & 1) * 2 + 1];
                __nv_bfloat162 hv;
                hv.x = __float2bfloat16(a);
                hv.y = __float2bfloat16(b);
                ph[q2] = *(uint32_t*)&hv;
                __nv_bfloat162 lv;
                lv.x = __float2bfloat16(a - __bfloat162float(hv.x));
                lv.y = __float2bfloat16(b - __bfloat162float(hv.y));
                pl[q2] = *(uint32_t*)&lv;
            }
            // trans ldmatrix: rows = keys ks*16 + (lane&7) + ((lane>>3)&1)*8,
            // octet = nb*2 + (lane>>4). Result r0/r1 = octet nb*2 (b0,b1),
            // r2/r3 = octet nb*2+1.
            uint32_t vrow = (uint32_t)(ks * 16 + (lane & 7) +
                                       ((lane >> 3) & 1) * 8);
#pragma unroll
            for (int nb = 0; nb < 4; nb++) {
                uint32_t vaddr = Vs + vrow * AP +
                                 (uint32_t)(nb * 2 + (lane >> 4)) * 16;
                uint32_t vh4[4], vl4[4];
                ldm4t(vh4, vaddr);
                ldm4t(vl4, vaddr + 128);
                mma16816(O[nb * 2 + 0], ph, &vh4[0]);
                mma16816(O[nb * 2 + 0], pl, &vh4[0]);
                mma16816(O[nb * 2 + 0], ph, &vl4[0]);
                mma16816(O[nb * 2 + 1], ph, &vh4[2]);
                mma16816(O[nb * 2 + 1], pl, &vh4[2]);
                mma16816(O[nb * 2 + 1], ph, &vl4[2]);
            }
        }
    }

    // Epilogue
#pragma unroll
    for (int rr = 0; rr < 2; rr++) {
        float inv = 1.f / ll[rr];
        size_t orow = (size_t)bh * Tr + seg * 512 + m0 + warp * 16 +
                      (lane >> 2) + rr * 8;
#pragma unroll
        for (int nn = 0; nn < 8; nn++) {
            float2 o2;
            o2.x = O[nn][rr * 2 + 0] * inv;
            o2.y = O[nn][rr * 2 + 1] * inv;
            *(float2*)&obr[orow * D_ + nn * 8 + (lane & 3) * 2] = o2;
        }
        if ((lane & 3) == 0) lbr[orow] = ml[rr] + logf(ll[rr]);
    }
}

// ---------------------------------------------------------------------------
// Combine branches with LSE weights; emit split bf16 y2 [8192, 2048]
// ---------------------------------------------------------------------------
__global__ __launch_bounds__(128) void combine_kernel(
    const float* __restrict__ o0, const float* __restrict__ o1,
    const float* __restrict__ o2,
    const float* __restrict__ l0, const float* __restrict__ l1,
    const float* __restrict__ l2,
    __nv_bfloat16* __restrict__ y2)
{
    int rowid = blockIdx.x * 128 + threadIdx.x;
    int bh = rowid >> 12;
    int t = rowid & 4095;
    int h = bh & (H_ - 1);
    int b = bh >> 4;

    float L0 = l0[(size_t)bh * 4096 + t];
    bool c1 = ((t & 1) == (h & 1));
    bool c2 = ((t & 3) == (h & 3));
    size_t i1 = (size_t)bh * 2048 + ((size_t)(t >> 10) << 9) + ((t & 1023) >> 1);
    size_t i2 = (size_t)bh * 1024 + ((size_t)(t >> 11) << 9) + ((t & 2047) >> 2);
    float L1 = c1 ? l1[i1] : -1e30f;
    float L2 = c2 ? l2[i2] : -1e30f;
    float m = fmaxf(L0, fmaxf(L1, L2));
    float w0 = __expf(L0 - m);
    float w1 = c1 ? __expf(L1 - m) : 0.f;
    float w2 = c2 ? __expf(L2 - m) : 0.f;
    float inv = 1.f / (w0 + w1 + w2);
    w0 *= inv; w1 *= inv; w2 *= inv;

    const float* p0 = o0 + ((size_t)bh * 4096 + t) * D_;
    const float* p1 = o1 + i1 * D_;
    const float* p2 = o2 + i2 * D_;
    size_t ybase = (size_t)(b * 4096 + t) * 2048 + h * D_;

#pragma unroll
    for (int d = 0; d < 64; d += 4) {
        float4 a0 = *(const float4*)&p0[d];
        float4 res = make_float4(w0 * a0.x, w0 * a0.y, w0 * a0.z, w0 * a0.w);
        if (c1) {
            float4 a1 = *(const float4*)&p1[d];
            res.x += w1 * a1.x; res.y += w1 * a1.y;
            res.z += w1 * a1.z; res.w += w1 * a1.w;
        }
        if (c2) {
            float4 a2 = *(const float4*)&p2[d];
            res.x += w2 * a2.x; res.y += w2 * a2.y;
            res.z += w2 * a2.z; res.w += w2 * a2.w;
        }
        __nv_bfloat162 h0, h1, lo0, lo1;
        h0.x = __float2bfloat16(res.x); h0.y = __float2bfloat16(res.y);
        h1.x = __float2bfloat16(res.z); h1.y = __float2bfloat16(res.w);
        lo0.x = __float2bfloat16(res.x - __bfloat162float(h0.x));
        lo0.y = __float2bfloat16(res.y - __bfloat162float(h0.y));
        lo1.x = __float2bfloat16(res.z - __bfloat162float(h1.x));
        lo1.y = __float2bfloat16(res.w - __bfloat162float(h1.y));
        *(__nv_bfloat162*)&y2[ybase + d] = h0;
        *(__nv_bfloat162*)&y2[ybase + d + 2] = h1;
        *(__nv_bfloat162*)&y2[ybase + 1024 + d] = lo0;
        *(__nv_bfloat162*)&y2[ybase + 1024 + d + 2] = lo1;
    }
}

// ---------------------------------------------------------------------------
// Launch
// ---------------------------------------------------------------------------
extern "C" void kernel_launch(void* const* d_in, const int* in_sizes, int n_in,
                              void* d_out, int out_size)
{
    (void)in_sizes; (void)n_in; (void)out_size;
    const float* x        = (const float*)d_in[0];
    const float* c_attn_w = (const float*)d_in[1];
    const float* c_attn_b = (const float*)d_in[2];
    const float* q_w      = (const float*)d_in[3];
    const float* q_b      = (const float*)d_in[4];
    const float* k_w      = (const float*)d_in[5];
    const float* k_b      = (const float*)d_in[6];
    const float* v_w      = (const float*)d_in[7];
    const float* v_b      = (const float*)d_in[8];
    const float* o_w      = (const float*)d_in[9];
    const float* o_b      = (const float*)d_in[10];
    float* out = (float*)d_out;

    __nv_bfloat16 *xs, *wqkv, *wo, *wcr, *wf, *y2, *qkvb;
    float *bf, *zero, *o0, *o1, *o2, *l0, *l1, *l2;
    cudaGetSymbolAddress((void**)&xs,   g_xs);
    cudaGetSymbolAddress((void**)&wqkv, g_wqkv);
    cudaGetSymbolAddress((void**)&wo,   g_wo);
    cudaGetSymbolAddress((void**)&wcr,  g_wcr);
    cudaGetSymbolAddress((void**)&wf,   g_wf);
    cudaGetSymbolAddress((void**)&bf,   g_bf);
    cudaGetSymbolAddress((void**)&zero, g_zero);
    cudaGetSymbolAddress((void**)&qkvb, g_qkvb);
    cudaGetSymbolAddress((void**)&y2,   g_y2);
    cudaGetSymbolAddress((void**)&o0,   g_o0);
    cudaGetSymbolAddress((void**)&o1,   g_o1);
    cudaGetSymbolAddress((void**)&o2,   g_o2);
    cudaGetSymbolAddress((void**)&l0,   g_l0);
    cudaGetSymbolAddress((void**)&l1,   g_l1);
    cudaGetSymbolAddress((void**)&l2,   g_l2);

    cudaFuncSetAttribute(gemm_mma, cudaFuncAttributeMaxDynamicSharedMemorySize,
                         GEMM_SMEM);
    cudaFuncSetAttribute(attn2, cudaFuncAttributeMaxDynamicSharedMemorySize,
                         ATTN2_SMEM);

    const size_t WSL = (size_t)1024 * 2048 * sizeof(__nv_bfloat16);  // 4 MB

    // 0) conversions (z-batched)
    xsplit<<<8192, 256>>>(x, xs);
    wsplitT4<<<dim3(32, 32, 4), dim3(32, 8)>>>(q_w, k_w, v_w, o_w, wqkv, wo);
    rowsplit3<<<dim3(1024, 3), 256>>>(c_attn_w, wcr);
    biasfold3<<<3, 1024>>>(c_attn_b, q_w, k_w, v_w, q_b, k_b, v_b, bf);

    // 1) fused-weight prep (single z-batched launch, one wave)
    gemm_mma<<<dim3(8, 8, 3), 256, GEMM_SMEM>>>(
        wcr, 2048, 0, 1024, wqkv, 2048, 0, 1024,
        zero, wf, 2048, 1024, 32, 3, 1.f, WSL, WSL, WSL);

    // 2) merged projection: q/k/v = x @ Wf + bf -> split bf16 [s][bh][t][hi|lo]
    gemm_mma<<<dim3(24, 64), 256, GEMM_SMEM>>>(
        xs, 2048, 0, 1024, wf, 2048, 0, 1024, bf,
        qkvb, 0, 0, 32, 1, 0.125f, 0, 0, 0);

    // 3) HMMA dilated attention, all branches in one launch
    attn2<<<dim3(4, 14, 32), 256, ATTN2_SMEM>>>(qkvb, o0, l0, o1, l1, o2, l2);

    // 4) combine -> split bf16 y2
    combine_kernel<<<dim3(B_ * H_ * T_ / 128), 128>>>(o0, o1, o2, l0, l1, l2,
                                                      y2);
    // 5) out = y @ o_w + o_b
    gemm_mma<<<dim3(8, 64), 256, GEMM_SMEM>>>(
        y2, 2048, 0, 1024, wo, 2048, 0, 1024, o_b,
        out, 1024, 0, 32, 0, 1.f, 0, 0, 0);
}